// round 9
// baseline (speedup 1.0000x reference)
#include <cuda_runtime.h>
#include <math.h>

#define Bn 2
#define Cn 64
#define Hn 192
#define Wn 192
#define HWn (Hn*Wn)
#define Gn 4
#define CGn 16
#define Kn 9

typedef unsigned long long ull;

// Scratch
__device__ float g_xnhwc[Bn*HWn*Cn];           // NHWC warp_ref
__device__ float g_mod[Bn*Gn*Kn*HWn];          // modulator
__device__ float g_wTu[Gn*Kn*4*16*4*4];        // reg_w as [g][k][cc][j2][q][e]

// ---------- packed fp32x2 helpers ----------
__device__ __forceinline__ ull pk2(float x) {
    ull r; unsigned u = __float_as_uint(x);
    asm("mov.b64 %0, {%1, %1};" : "=l"(r) : "r"(u));
    return r;
}
__device__ __forceinline__ void fma2(ull& d, ull a, ull b) {
    asm("fma.rn.f32x2 %0, %1, %2, %0;" : "+l"(d) : "l"(a), "l"(b));
}
__device__ __forceinline__ float2 upk(ull p) {
    unsigned lo, hi;
    asm("mov.b64 {%0, %1}, %2;" : "=r"(lo), "=r"(hi) : "l"(p));
    return make_float2(__uint_as_float(lo), __uint_as_float(hi));
}

// ---------------------------------------------------------------------------
// NCHW -> NHWC transpose of warp_ref
// ---------------------------------------------------------------------------
__global__ void k_transpose(const float* __restrict__ x) {
    __shared__ float t[32][33];
    int b   = blockIdx.z;
    int hw0 = blockIdx.x * 32;
    int c0  = blockIdx.y * 32;
    #pragma unroll
    for (int i = 0; i < 4; i++) {
        int c = c0 + threadIdx.y + i*8;
        t[threadIdx.y + i*8][threadIdx.x] = x[(b*Cn + c)*HWn + hw0 + threadIdx.x];
    }
    __syncthreads();
    #pragma unroll
    for (int i = 0; i < 4; i++) {
        int hw = hw0 + threadIdx.y + i*8;
        g_xnhwc[(size_t)(b*HWn + hw)*Cn + c0 + threadIdx.x] = t[threadIdx.x][threadIdx.y + i*8];
    }
}

// reg_w [co][cin][k] -> g_wTu [g][k][cc][j2][q][e]  (c = q*4+cc, co = j2*4+e)
__global__ void k_wprep(const float* __restrict__ rw) {
    int i = blockIdx.x*256 + threadIdx.x;
    if (i >= Gn*Kn*4*16*4*4) return;
    int e  = i & 3;
    int q  = (i >> 2) & 3;
    int j2 = (i >> 4) & 15;
    int cc = (i >> 8) & 3;
    int k  = (i >> 10) % 9;
    int g  = i / 9216;
    int c  = q*4 + cc;
    int co = j2*4 + e;
    g_wTu[i] = rw[(size_t)(co*Cn + g*CGn + c)*Kn + k];
}

// ---------------------------------------------------------------------------
// Offset conv (known good).
// ---------------------------------------------------------------------------
__global__ void k_offset(const float* __restrict__ wr, const float* __restrict__ src,
                         const float* __restrict__ ow, const float* __restrict__ ob,
                         float* __restrict__ offout) {
    __shared__ float sT[8*18*35];
    __shared__ float sWp[8*9*20];
    int tid = threadIdx.x;
    int g = blockIdx.y, b = blockIdx.z;
    int th = (blockIdx.x / 6) * 16, tw = (blockIdx.x % 6) * 32;
    int lyy = tid >> 4, lxx = tid & 15;

    float4 acc0[5], acc1[5];
    #pragma unroll
    for (int j = 0; j < 5; j++) { acc0[j] = make_float4(0,0,0,0); acc1[j] = make_float4(0,0,0,0); }

    for (int chunk = 0; chunk < 4; chunk++) {
        const float* base = (chunk < 2 ? wr : src) + (size_t)(b*Cn + g*CGn + (chunk&1)*8)*HWn;
        __syncthreads();
        for (int i = tid; i < 1440; i += 256) {
            int c = i / 180; int r = i % 180; int widx = r / 20; int o = r % 20;
            float v = 0.f;
            if (o < 18) v = ow[(size_t)(o*32 + chunk*8 + c)*9 + widx];
            sWp[i] = v;
        }
        for (int i = tid; i < 8*18*35; i += 256) {
            int c = i / 630; int r2 = i % 630; int rr = r2 / 35; int cc = r2 % 35;
            int y = th + rr - 1, x = tw + cc - 1;
            float v = 0.f;
            if (cc < 34 && (unsigned)y < (unsigned)Hn && (unsigned)x < (unsigned)Wn)
                v = base[c*HWn + y*Wn + x];
            sT[i] = v;
        }
        __syncthreads();
        for (int c = 0; c < 8; c++) {
            #pragma unroll
            for (int kh = 0; kh < 3; kh++) {
                const float* rowp = sT + c*630 + (lyy+kh)*35 + 2*lxx;
                float xv[4];
                xv[0] = rowp[0]; xv[1] = rowp[1]; xv[2] = rowp[2]; xv[3] = rowp[3];
                #pragma unroll
                for (int kw = 0; kw < 3; kw++) {
                    const float4* wp = (const float4*)(sWp + (c*9 + kh*3 + kw)*20);
                    float a0 = xv[kw], a1 = xv[kw+1];
                    #pragma unroll
                    for (int j = 0; j < 5; j++) {
                        float4 wv = wp[j];
                        acc0[j].x = fmaf(a0, wv.x, acc0[j].x); acc1[j].x = fmaf(a1, wv.x, acc1[j].x);
                        acc0[j].y = fmaf(a0, wv.y, acc0[j].y); acc1[j].y = fmaf(a1, wv.y, acc1[j].y);
                        acc0[j].z = fmaf(a0, wv.z, acc0[j].z); acc1[j].z = fmaf(a1, wv.z, acc1[j].z);
                        acc0[j].w = fmaf(a0, wv.w, acc0[j].w); acc1[j].w = fmaf(a1, wv.w, acc1[j].w);
                    }
                }
            }
        }
    }
    int h = th + lyy, w = tw + 2*lxx;
    const float* a0 = (const float*)acc0;
    const float* a1 = (const float*)acc1;
    #pragma unroll
    for (int o = 0; o < 18; o++) {
        float bo = ob[o];
        float2 r;
        r.x = 50.f * tanhf(0.5f * (a0[o] + bo));
        r.y = 50.f * tanhf(0.5f * (a1[o] + bo));
        *(float2*)(offout + (size_t)(b*72 + g*18 + o)*HWn + h*Wn + w) = r;
    }
}

// ---------------------------------------------------------------------------
// Modulator conv (known good).
// ---------------------------------------------------------------------------
__global__ void k_mod(const float* __restrict__ wr, const float* __restrict__ mw,
                      const float* __restrict__ mb) {
    __shared__ float sT[8*18*35];
    __shared__ float sWp[8*9*20];
    int tid = threadIdx.x;
    int obase = blockIdx.y * 18;
    int b = blockIdx.z;
    int th = (blockIdx.x / 6) * 16, tw = (blockIdx.x % 6) * 32;
    int lyy = tid >> 4, lxx = tid & 15;

    float4 acc0[5], acc1[5];
    #pragma unroll
    for (int j = 0; j < 5; j++) { acc0[j] = make_float4(0,0,0,0); acc1[j] = make_float4(0,0,0,0); }

    for (int chunk = 0; chunk < 8; chunk++) {
        const float* base = wr + (size_t)(b*Cn + chunk*8)*HWn;
        __syncthreads();
        for (int i = tid; i < 1440; i += 256) {
            int c = i / 180; int r = i % 180; int widx = r / 20; int o = r % 20;
            float v = 0.f;
            if (o < 18) v = mw[(size_t)((obase + o)*Cn + chunk*8 + c)*9 + widx];
            sWp[i] = v;
        }
        for (int i = tid; i < 8*18*35; i += 256) {
            int c = i / 630; int r2 = i % 630; int rr = r2 / 35; int cc = r2 % 35;
            int y = th + rr - 1, x = tw + cc - 1;
            float v = 0.f;
            if (cc < 34 && (unsigned)y < (unsigned)Hn && (unsigned)x < (unsigned)Wn)
                v = base[c*HWn + y*Wn + x];
            sT[i] = v;
        }
        __syncthreads();
        for (int c = 0; c < 8; c++) {
            #pragma unroll
            for (int kh = 0; kh < 3; kh++) {
                const float* rowp = sT + c*630 + (lyy+kh)*35 + 2*lxx;
                float xv[4];
                xv[0] = rowp[0]; xv[1] = rowp[1]; xv[2] = rowp[2]; xv[3] = rowp[3];
                #pragma unroll
                for (int kw = 0; kw < 3; kw++) {
                    const float4* wp = (const float4*)(sWp + (c*9 + kh*3 + kw)*20);
                    float a0 = xv[kw], a1 = xv[kw+1];
                    #pragma unroll
                    for (int j = 0; j < 5; j++) {
                        float4 wv = wp[j];
                        acc0[j].x = fmaf(a0, wv.x, acc0[j].x); acc1[j].x = fmaf(a1, wv.x, acc1[j].x);
                        acc0[j].y = fmaf(a0, wv.y, acc0[j].y); acc1[j].y = fmaf(a1, wv.y, acc1[j].y);
                        acc0[j].z = fmaf(a0, wv.z, acc0[j].z); acc1[j].z = fmaf(a1, wv.z, acc1[j].z);
                        acc0[j].w = fmaf(a0, wv.w, acc0[j].w); acc1[j].w = fmaf(a1, wv.w, acc1[j].w);
                    }
                }
            }
        }
    }
    int h = th + lyy, w = tw + 2*lxx;
    const float* a0 = (const float*)acc0;
    const float* a1 = (const float*)acc1;
    #pragma unroll
    for (int o = 0; o < 18; o++) {
        float bo = mb[obase + o];
        float2 r;
        r.x = 1.f + tanhf(0.5f * (a0[o] + bo));
        r.y = 1.f + tanhf(0.5f * (a1[o] + bo));
        *(float2*)(g_mod + (size_t)(b*36 + obase + o)*HWn + h*Wn + w) = r;
    }
}

// ---------------------------------------------------------------------------
// Deformable conv v5 = R7 dataflow + software-pipelined gather.
// Thread = (pixel, channel-quad q), full 64 co per thread (32 ull accs).
// Raw corner loads for step k+1 are issued BEFORE step k's contraction so the
// L2 latency hides under the 128 fma2 of the contraction.
// ---------------------------------------------------------------------------
__global__ void __launch_bounds__(256, 2) k_deform(
        const float* __restrict__ offmap, float* __restrict__ out) {
    __shared__ float sW[Kn*4*16*4*4];   // 9216 floats = 36 KB
    int tid  = threadIdx.x;
    int lane = tid & 31;
    int pxw  = lane >> 2;            // pixel within warp (0..7)
    int q    = lane & 3;             // channel-quad (0..3)
    int px   = (tid >> 5)*8 + pxw;   // pixel within block (0..63)
    int p0   = blockIdx.x * 64;
    int b    = p0 / HWn;
    int hw   = p0 - b*HWn + px;
    int h    = hw / Wn, w = hw - h*Wn;

    ull acc[32];
    #pragma unroll
    for (int j = 0; j < 32; j++) acc[j] = 0ull;

    const float* xb = g_xnhwc + (size_t)b*HWn*Cn;

    for (int g = 0; g < Gn; g++) {
        __syncthreads();
        {   // coalesced linear copy (pre-baked layout)
            const float* wg = g_wTu + g*9216;
            for (int i = tid; i < 9216; i += 256) sW[i] = wg[i];
        }
        __syncthreads();

        const float* offb = offmap + (size_t)(b*72 + g*18)*HWn + hw;
        const float* modb = g_mod  + (size_t)(b*36 + g*9 )*HWn + hw;
        const float* xg   = xb + g*CGn + q*4;

        // pipeline state: raw corners + bilinear weights for step "cur"
        float4 r0, r1, r2, r3;
        float cw0, cw1, cw2, cw3;
        float oy = offb[0];
        float ox = offb[HWn];
        float m  = modb[0];

        // issue loads for k = 0
        {
            float yf = oy + (float)(h - 1);
            float xf = ox + (float)(w - 1);
            float y0f = floorf(yf), x0f = floorf(xf);
            int   y0  = (int)y0f,   x0  = (int)x0f;
            float ly = yf - y0f, lx = xf - x0f;
            cw0 = (1.f-ly)*(1.f-lx)*m;
            cw1 = (1.f-ly)*lx*m;
            cw2 = ly*(1.f-lx)*m;
            cw3 = ly*lx*m;
            bool vy0 = (unsigned)y0 < (unsigned)Hn, vy1 = (unsigned)(y0+1) < (unsigned)Hn;
            bool vx0 = (unsigned)x0 < (unsigned)Wn, vx1 = (unsigned)(x0+1) < (unsigned)Wn;
            float4 z = make_float4(0,0,0,0);
            r0 = (vy0&&vx0) ? *(const float4*)(xg + (size_t)(y0*Wn     + x0    )*Cn) : z;
            r1 = (vy0&&vx1) ? *(const float4*)(xg + (size_t)(y0*Wn     + x0 + 1)*Cn) : z;
            r2 = (vy1&&vx0) ? *(const float4*)(xg + (size_t)((y0+1)*Wn + x0    )*Cn) : z;
            r3 = (vy1&&vx1) ? *(const float4*)(xg + (size_t)((y0+1)*Wn + x0 + 1)*Cn) : z;
        }

        #pragma unroll 1
        for (int k = 0; k < 9; k++) {
            // prefetch offsets for k+1
            float noy = 0.f, nox = 0.f, nm = 0.f;
            if (k < 8) {
                noy = offb[(2*k+2)*HWn];
                nox = offb[(2*k+3)*HWn];
                nm  = modb[(k+1)*HWn];
            }
            // combine current raw corners -> v
            float4 v;
            v.x = cw0*r0.x + cw1*r1.x + cw2*r2.x + cw3*r3.x;
            v.y = cw0*r0.y + cw1*r1.y + cw2*r2.y + cw3*r3.y;
            v.z = cw0*r0.z + cw1*r1.z + cw2*r2.z + cw3*r3.z;
            v.w = cw0*r0.w + cw1*r1.w + cw2*r2.w + cw3*r3.w;

            // issue loads for k+1 (in flight during contraction below)
            if (k < 8) {
                int kk = k + 1;
                float yf = noy + (float)(kk/3 + h - 1);
                float xf = nox + (float)(kk%3 + w - 1);
                float y0f = floorf(yf), x0f = floorf(xf);
                int   y0  = (int)y0f,   x0  = (int)x0f;
                float ly = yf - y0f, lx = xf - x0f;
                cw0 = (1.f-ly)*(1.f-lx)*nm;
                cw1 = (1.f-ly)*lx*nm;
                cw2 = ly*(1.f-lx)*nm;
                cw3 = ly*lx*nm;
                bool vy0 = (unsigned)y0 < (unsigned)Hn, vy1 = (unsigned)(y0+1) < (unsigned)Hn;
                bool vx0 = (unsigned)x0 < (unsigned)Wn, vx1 = (unsigned)(x0+1) < (unsigned)Wn;
                float4 z = make_float4(0,0,0,0);
                r0 = (vy0&&vx0) ? *(const float4*)(xg + (size_t)(y0*Wn     + x0    )*Cn) : z;
                r1 = (vy0&&vx1) ? *(const float4*)(xg + (size_t)(y0*Wn     + x0 + 1)*Cn) : z;
                r2 = (vy1&&vx0) ? *(const float4*)(xg + (size_t)((y0+1)*Wn + x0    )*Cn) : z;
                r3 = (vy1&&vx1) ? *(const float4*)(xg + (size_t)((y0+1)*Wn + x0 + 1)*Cn) : z;
            }

            // contract my 4 channels into all 64 co
            float cv[4] = {v.x, v.y, v.z, v.w};
            #pragma unroll
            for (int cc = 0; cc < 4; cc++) {
                ull vp = pk2(cv[cc]);
                const float* rp = sW + ((k*4 + cc)*16)*16 + q*4;
                #pragma unroll
                for (int j2 = 0; j2 < 16; j2++) {
                    ulonglong2 wv = *(const ulonglong2*)(rp + j2*16);
                    fma2(acc[2*j2],   vp, wv.x);
                    fma2(acc[2*j2+1], vp, wv.y);
                }
            }
        }
    }

    // butterfly reduction over the 4 q-lanes of each pixel
    float2 af[32];
    #pragma unroll
    for (int t = 0; t < 32; t++) af[t] = upk(acc[t]);
    #pragma unroll
    for (int t = 0; t < 32; t++) {
        af[t].x += __shfl_xor_sync(0xffffffffu, af[t].x, 1);
        af[t].y += __shfl_xor_sync(0xffffffffu, af[t].y, 1);
        af[t].x += __shfl_xor_sync(0xffffffffu, af[t].x, 2);
        af[t].y += __shfl_xor_sync(0xffffffffu, af[t].y, 2);
    }

    // lane q writes co pairs t = q*8 .. q*8+7  (co = 2t, 2t+1)
    float* ob = out + (size_t)b*Cn*HWn + hw;
    #pragma unroll
    for (int r = 0; r < 8; r++) {
        int t = q*8 + r;
        ob[(size_t)(2*t  )*HWn] = af[t].x;
        ob[(size_t)(2*t+1)*HWn] = af[t].y;
    }
}

// ---------------------------------------------------------------------------
extern "C" void kernel_launch(void* const* d_in, const int* in_sizes, int n_in,
                              void* d_out, int out_size) {
    const float* wr  = (const float*)d_in[0];
    const float* src = (const float*)d_in[1];
    const float* ow  = (const float*)d_in[2];
    const float* obv = (const float*)d_in[3];
    const float* mw  = (const float*)d_in[4];
    const float* mbv = (const float*)d_in[5];
    const float* rw  = (const float*)d_in[6];

    float* out    = (float*)d_out;
    float* offout = out + (size_t)Bn*Cn*HWn;

    k_transpose<<<dim3(HWn/32, 2, Bn), dim3(32, 8)>>>(wr);
    k_wprep   <<<(Gn*Kn*4*16*4*4 + 255)/256, 256>>>(rw);
    k_offset  <<<dim3(72, Gn, Bn), 256>>>(wr, src, ow, obv, offout);
    k_mod     <<<dim3(72, 2, Bn), 256>>>(wr, mw, mbv);
    k_deform  <<<Bn*HWn/64, 256>>>(offout, out);
}

// round 11
// speedup vs baseline: 1.4151x; 1.4151x over previous
#include <cuda_runtime.h>
#include <math.h>

#define Bn 2
#define Cn 64
#define Hn 192
#define Wn 192
#define HWn (Hn*Wn)
#define Gn 4
#define CGn 16
#define Kn 9

typedef unsigned long long ull;

// Scratch
__device__ float g_xnhwc[Bn*HWn*Cn];           // NHWC warp_ref
__device__ float g_mod[Bn*Gn*Kn*HWn];          // modulator
__device__ float g_wTu[Gn*Kn*8*16*2*4];        // reg_w as [g][k][cc8][j2][q2][e4]

// ---------- packed fp32x2 helpers ----------
__device__ __forceinline__ ull pk2(float x) {
    ull r; unsigned u = __float_as_uint(x);
    asm("mov.b64 %0, {%1, %1};" : "=l"(r) : "r"(u));
    return r;
}
__device__ __forceinline__ void fma2(ull& d, ull a, ull b) {
    asm("fma.rn.f32x2 %0, %1, %2, %0;" : "+l"(d) : "l"(a), "l"(b));
}
__device__ __forceinline__ float2 upk(ull p) {
    unsigned lo, hi;
    asm("mov.b64 {%0, %1}, %2;" : "=r"(lo), "=r"(hi) : "l"(p));
    return make_float2(__uint_as_float(lo), __uint_as_float(hi));
}

// ---------------------------------------------------------------------------
// NCHW -> NHWC transpose of warp_ref
// ---------------------------------------------------------------------------
__global__ void k_transpose(const float* __restrict__ x) {
    __shared__ float t[32][33];
    int b   = blockIdx.z;
    int hw0 = blockIdx.x * 32;
    int c0  = blockIdx.y * 32;
    #pragma unroll
    for (int i = 0; i < 4; i++) {
        int c = c0 + threadIdx.y + i*8;
        t[threadIdx.y + i*8][threadIdx.x] = x[(b*Cn + c)*HWn + hw0 + threadIdx.x];
    }
    __syncthreads();
    #pragma unroll
    for (int i = 0; i < 4; i++) {
        int hw = hw0 + threadIdx.y + i*8;
        g_xnhwc[(size_t)(b*HWn + hw)*Cn + c0 + threadIdx.x] = t[threadIdx.x][threadIdx.y + i*8];
    }
}

// reg_w [co][cin][k] -> g_wTu [g][k][cc8][j2][q2][e4]
//   cin = g*16 + q*8 + cc ; co = j2*4 + e
__global__ void k_wprep(const float* __restrict__ rw) {
    int i = blockIdx.x*256 + threadIdx.x;
    if (i >= Gn*Kn*1024) return;
    int e  = i & 3;
    int q  = (i >> 2) & 1;
    int j2 = (i >> 3) & 15;
    int cc = (i >> 7) & 7;
    int gk = i >> 10;
    int k  = gk % 9;
    int g  = gk / 9;
    int c  = q*8 + cc;
    int co = j2*4 + e;
    g_wTu[i] = rw[(size_t)(co*Cn + g*CGn + c)*Kn + k];
}

// ---------------------------------------------------------------------------
// Offset conv (known good).
// ---------------------------------------------------------------------------
__global__ void k_offset(const float* __restrict__ wr, const float* __restrict__ src,
                         const float* __restrict__ ow, const float* __restrict__ ob,
                         float* __restrict__ offout) {
    __shared__ float sT[8*18*35];
    __shared__ float sWp[8*9*20];
    int tid = threadIdx.x;
    int g = blockIdx.y, b = blockIdx.z;
    int th = (blockIdx.x / 6) * 16, tw = (blockIdx.x % 6) * 32;
    int lyy = tid >> 4, lxx = tid & 15;

    float4 acc0[5], acc1[5];
    #pragma unroll
    for (int j = 0; j < 5; j++) { acc0[j] = make_float4(0,0,0,0); acc1[j] = make_float4(0,0,0,0); }

    for (int chunk = 0; chunk < 4; chunk++) {
        const float* base = (chunk < 2 ? wr : src) + (size_t)(b*Cn + g*CGn + (chunk&1)*8)*HWn;
        __syncthreads();
        for (int i = tid; i < 1440; i += 256) {
            int c = i / 180; int r = i % 180; int widx = r / 20; int o = r % 20;
            float v = 0.f;
            if (o < 18) v = ow[(size_t)(o*32 + chunk*8 + c)*9 + widx];
            sWp[i] = v;
        }
        for (int i = tid; i < 8*18*35; i += 256) {
            int c = i / 630; int r2 = i % 630; int rr = r2 / 35; int cc = r2 % 35;
            int y = th + rr - 1, x = tw + cc - 1;
            float v = 0.f;
            if (cc < 34 && (unsigned)y < (unsigned)Hn && (unsigned)x < (unsigned)Wn)
                v = base[c*HWn + y*Wn + x];
            sT[i] = v;
        }
        __syncthreads();
        for (int c = 0; c < 8; c++) {
            #pragma unroll
            for (int kh = 0; kh < 3; kh++) {
                const float* rowp = sT + c*630 + (lyy+kh)*35 + 2*lxx;
                float xv[4];
                xv[0] = rowp[0]; xv[1] = rowp[1]; xv[2] = rowp[2]; xv[3] = rowp[3];
                #pragma unroll
                for (int kw = 0; kw < 3; kw++) {
                    const float4* wp = (const float4*)(sWp + (c*9 + kh*3 + kw)*20);
                    float a0 = xv[kw], a1 = xv[kw+1];
                    #pragma unroll
                    for (int j = 0; j < 5; j++) {
                        float4 wv = wp[j];
                        acc0[j].x = fmaf(a0, wv.x, acc0[j].x); acc1[j].x = fmaf(a1, wv.x, acc1[j].x);
                        acc0[j].y = fmaf(a0, wv.y, acc0[j].y); acc1[j].y = fmaf(a1, wv.y, acc1[j].y);
                        acc0[j].z = fmaf(a0, wv.z, acc0[j].z); acc1[j].z = fmaf(a1, wv.z, acc1[j].z);
                        acc0[j].w = fmaf(a0, wv.w, acc0[j].w); acc1[j].w = fmaf(a1, wv.w, acc1[j].w);
                    }
                }
            }
        }
    }
    int h = th + lyy, w = tw + 2*lxx;
    const float* a0 = (const float*)acc0;
    const float* a1 = (const float*)acc1;
    #pragma unroll
    for (int o = 0; o < 18; o++) {
        float bo = ob[o];
        float2 r;
        r.x = 50.f * tanhf(0.5f * (a0[o] + bo));
        r.y = 50.f * tanhf(0.5f * (a1[o] + bo));
        *(float2*)(offout + (size_t)(b*72 + g*18 + o)*HWn + h*Wn + w) = r;
    }
}

// ---------------------------------------------------------------------------
// Modulator conv (known good).
// ---------------------------------------------------------------------------
__global__ void k_mod(const float* __restrict__ wr, const float* __restrict__ mw,
                      const float* __restrict__ mb) {
    __shared__ float sT[8*18*35];
    __shared__ float sWp[8*9*20];
    int tid = threadIdx.x;
    int obase = blockIdx.y * 18;
    int b = blockIdx.z;
    int th = (blockIdx.x / 6) * 16, tw = (blockIdx.x % 6) * 32;
    int lyy = tid >> 4, lxx = tid & 15;

    float4 acc0[5], acc1[5];
    #pragma unroll
    for (int j = 0; j < 5; j++) { acc0[j] = make_float4(0,0,0,0); acc1[j] = make_float4(0,0,0,0); }

    for (int chunk = 0; chunk < 8; chunk++) {
        const float* base = wr + (size_t)(b*Cn + chunk*8)*HWn;
        __syncthreads();
        for (int i = tid; i < 1440; i += 256) {
            int c = i / 180; int r = i % 180; int widx = r / 20; int o = r % 20;
            float v = 0.f;
            if (o < 18) v = mw[(size_t)((obase + o)*Cn + chunk*8 + c)*9 + widx];
            sWp[i] = v;
        }
        for (int i = tid; i < 8*18*35; i += 256) {
            int c = i / 630; int r2 = i % 630; int rr = r2 / 35; int cc = r2 % 35;
            int y = th + rr - 1, x = tw + cc - 1;
            float v = 0.f;
            if (cc < 34 && (unsigned)y < (unsigned)Hn && (unsigned)x < (unsigned)Wn)
                v = base[c*HWn + y*Wn + x];
            sT[i] = v;
        }
        __syncthreads();
        for (int c = 0; c < 8; c++) {
            #pragma unroll
            for (int kh = 0; kh < 3; kh++) {
                const float* rowp = sT + c*630 + (lyy+kh)*35 + 2*lxx;
                float xv[4];
                xv[0] = rowp[0]; xv[1] = rowp[1]; xv[2] = rowp[2]; xv[3] = rowp[3];
                #pragma unroll
                for (int kw = 0; kw < 3; kw++) {
                    const float4* wp = (const float4*)(sWp + (c*9 + kh*3 + kw)*20);
                    float a0 = xv[kw], a1 = xv[kw+1];
                    #pragma unroll
                    for (int j = 0; j < 5; j++) {
                        float4 wv = wp[j];
                        acc0[j].x = fmaf(a0, wv.x, acc0[j].x); acc1[j].x = fmaf(a1, wv.x, acc1[j].x);
                        acc0[j].y = fmaf(a0, wv.y, acc0[j].y); acc1[j].y = fmaf(a1, wv.y, acc1[j].y);
                        acc0[j].z = fmaf(a0, wv.z, acc0[j].z); acc1[j].z = fmaf(a1, wv.z, acc1[j].z);
                        acc0[j].w = fmaf(a0, wv.w, acc0[j].w); acc1[j].w = fmaf(a1, wv.w, acc1[j].w);
                    }
                }
            }
        }
    }
    int h = th + lyy, w = tw + 2*lxx;
    const float* a0 = (const float*)acc0;
    const float* a1 = (const float*)acc1;
    #pragma unroll
    for (int o = 0; o < 18; o++) {
        float bo = mb[obase + o];
        float2 r;
        r.x = 1.f + tanhf(0.5f * (a0[o] + bo));
        r.y = 1.f + tanhf(0.5f * (a1[o] + bo));
        *(float2*)(g_mod + (size_t)(b*36 + obase + o)*HWn + h*Wn + w) = r;
    }
}

// ---------------------------------------------------------------------------
// Deformable conv v6: thread = (pixel, channel-HALF q in {0,1}).
// Lane q gathers 8 channels (2x float4, 8 LDGs in flight per k) and contracts
// them into all 64 co (32 f32x2 accs). Per-warp k-phase rotation decorrelates
// memory stalls across the block's warps. Butterfly (xor 1) at the end.
// ---------------------------------------------------------------------------
__global__ void __launch_bounds__(256, 2) k_deform(
        const float* __restrict__ offmap, float* __restrict__ out) {
    __shared__ float sW[Gn == 4 ? Kn*1024 : 0];   // [k][cc8][j2][q2][e4] = 9216 floats
    int tid  = threadIdx.x;
    int lane = tid & 31;
    int pxw  = lane >> 1;             // pixel within warp (0..15)
    int q    = lane & 1;              // channel half (0..1)
    int wid  = tid >> 5;
    int px   = wid*16 + pxw;          // pixel within block (0..127)
    int p0   = blockIdx.x * 128;
    int b    = p0 / HWn;
    int hw   = p0 - b*HWn + px;
    int h    = hw / Wn, w = hw - h*Wn;
    int k0   = wid % 9;               // per-warp k phase

    ull acc[32];
    #pragma unroll
    for (int j = 0; j < 32; j++) acc[j] = 0ull;

    const float* xb = g_xnhwc + (size_t)b*HWn*Cn;

    for (int g = 0; g < Gn; g++) {
        __syncthreads();
        {   // coalesced linear copy (pre-baked layout)
            const float* wg = g_wTu + g*(Kn*1024);
            for (int i = tid; i < Kn*1024; i += 256) sW[i] = wg[i];
        }
        __syncthreads();

        const float* offb = offmap + (size_t)(b*72 + g*18)*HWn + hw;
        const float* modb = g_mod  + (size_t)(b*36 + g*9 )*HWn + hw;
        const float* xg   = xb + g*CGn + q*8;

        #pragma unroll 1
        for (int kk = 0; kk < 9; kk++) {
            int k = kk + k0; if (k >= 9) k -= 9;
            // ---- gather: this lane's 8 channels of its pixel ----
            float oy = offb[(2*k  )*HWn];
            float ox = offb[(2*k+1)*HWn];
            float m  = modb[k*HWn];
            float yf = oy + (float)(k/3 + h - 1);
            float xf = ox + (float)(k%3 + w - 1);
            float y0f = floorf(yf), x0f = floorf(xf);
            int   y0  = (int)y0f,   x0  = (int)x0f;
            float ly = yf - y0f, lx = xf - x0f;
            float cw0 = (1.f-ly)*(1.f-lx)*m;
            float cw1 = (1.f-ly)*lx*m;
            float cw2 = ly*(1.f-lx)*m;
            float cw3 = ly*lx*m;
            float4 va = make_float4(0.f,0.f,0.f,0.f);
            float4 vb = make_float4(0.f,0.f,0.f,0.f);
            #pragma unroll
            for (int corner = 0; corner < 4; corner++) {
                int yi = y0 + (corner >> 1);
                int xi = x0 + (corner & 1);
                float wc = (corner==0)?cw0:(corner==1)?cw1:(corner==2)?cw2:cw3;
                if ((unsigned)yi < (unsigned)Hn && (unsigned)xi < (unsigned)Wn) {
                    const float4* pp = (const float4*)(xg + (size_t)(yi*Wn + xi)*Cn);
                    float4 xa = pp[0];
                    float4 xbv = pp[1];
                    va.x = fmaf(wc, xa.x, va.x);  va.y = fmaf(wc, xa.y, va.y);
                    va.z = fmaf(wc, xa.z, va.z);  va.w = fmaf(wc, xa.w, va.w);
                    vb.x = fmaf(wc, xbv.x, vb.x); vb.y = fmaf(wc, xbv.y, vb.y);
                    vb.z = fmaf(wc, xbv.z, vb.z); vb.w = fmaf(wc, xbv.w, vb.w);
                }
            }
            // ---- contract my 8 channels into all 64 co ----
            float cv[8] = {va.x, va.y, va.z, va.w, vb.x, vb.y, vb.z, vb.w};
            #pragma unroll
            for (int cc = 0; cc < 8; cc++) {
                ull vp = pk2(cv[cc]);
                const float* rp = sW + ((k*8 + cc) << 7) + q*4;
                #pragma unroll
                for (int j2 = 0; j2 < 16; j2++) {
                    ulonglong2 wv = *(const ulonglong2*)(rp + j2*8);
                    fma2(acc[2*j2],   vp, wv.x);
                    fma2(acc[2*j2+1], vp, wv.y);
                }
            }
        }
    }

    // butterfly reduction over the 2 q-lanes of each pixel
    float2 af[32];
    #pragma unroll
    for (int t = 0; t < 32; t++) af[t] = upk(acc[t]);
    #pragma unroll
    for (int t = 0; t < 32; t++) {
        af[t].x += __shfl_xor_sync(0xffffffffu, af[t].x, 1);
        af[t].y += __shfl_xor_sync(0xffffffffu, af[t].y, 1);
    }

    // lane q writes co pairs t = q*16 .. q*16+15  (co = 2t, 2t+1)
    float* ob = out + (size_t)b*Cn*HWn + hw;
    #pragma unroll
    for (int r = 0; r < 16; r++) {
        int t = q*16 + r;
        ob[(size_t)(2*t  )*HWn] = af[t].x;
        ob[(size_t)(2*t+1)*HWn] = af[t].y;
    }
}

// ---------------------------------------------------------------------------
extern "C" void kernel_launch(void* const* d_in, const int* in_sizes, int n_in,
                              void* d_out, int out_size) {
    const float* wr  = (const float*)d_in[0];
    const float* src = (const float*)d_in[1];
    const float* ow  = (const float*)d_in[2];
    const float* obv = (const float*)d_in[3];
    const float* mw  = (const float*)d_in[4];
    const float* mbv = (const float*)d_in[5];
    const float* rw  = (const float*)d_in[6];

    float* out    = (float*)d_out;
    float* offout = out + (size_t)Bn*Cn*HWn;

    k_transpose<<<dim3(HWn/32, 2, Bn), dim3(32, 8)>>>(wr);
    k_wprep   <<<(Gn*Kn*1024 + 255)/256, 256>>>(rw);
    k_offset  <<<dim3(72, Gn, Bn), 256>>>(wr, src, ow, obv, offout);
    k_mod     <<<dim3(72, 2, Bn), 256>>>(wr, mw, mbv);
    k_deform  <<<Bn*HWn/128, 256>>>(offout, out);
}

// round 12
// speedup vs baseline: 1.4761x; 1.0431x over previous
#include <cuda_runtime.h>
#include <math.h>

#define Bn 2
#define Cn 64
#define Hn 192
#define Wn 192
#define HWn (Hn*Wn)
#define Gn 4
#define CGn 16
#define Kn 9

typedef unsigned long long ull;

// Scratch
__device__ float g_xnhwc[Bn*HWn*Cn];           // NHWC warp_ref
__device__ float g_mod[Bn*Gn*Kn*HWn];          // modulator
__device__ float g_wTu[Gn*Kn*8*16*2*4];        // reg_w as [g][k][cc8][j2][q2][e4]

// ---------- packed fp32x2 helpers ----------
__device__ __forceinline__ ull pk2(float x) {
    ull r; unsigned u = __float_as_uint(x);
    asm("mov.b64 %0, {%1, %1};" : "=l"(r) : "r"(u));
    return r;
}
__device__ __forceinline__ void fma2(ull& d, ull a, ull b) {
    asm("fma.rn.f32x2 %0, %1, %2, %0;" : "+l"(d) : "l"(a), "l"(b));
}
__device__ __forceinline__ float2 upk(ull p) {
    unsigned lo, hi;
    asm("mov.b64 {%0, %1}, %2;" : "=r"(lo), "=r"(hi) : "l"(p));
    return make_float2(__uint_as_float(lo), __uint_as_float(hi));
}

// ---------------------------------------------------------------------------
// Fused prep kernel: role decoded from blockIdx.x.
//   [0, 576)      offset conv blocks
//   [576, 864)    mod conv blocks
//   [864, 5472)   NCHW->NHWC transpose blocks
//   [5472, 5616)  weight re-layout blocks
// ---------------------------------------------------------------------------
#define NB_OFF 576
#define NB_MOD 288
#define NB_TR  4608
#define NB_WP  144
#define NB_ALL (NB_OFF + NB_MOD + NB_TR + NB_WP)

__global__ void __launch_bounds__(256) k_prep(
        const float* __restrict__ wr, const float* __restrict__ src,
        const float* __restrict__ ow, const float* __restrict__ obv,
        const float* __restrict__ mw, const float* __restrict__ mbv,
        const float* __restrict__ rw, float* __restrict__ offout) {
    __shared__ float sT[8*18*35];   // 5040 floats (also reused by transpose)
    __shared__ float sWp[8*9*20];   // 1440 floats
    int tid = threadIdx.x;
    int bid = blockIdx.x;

    if (bid < NB_OFF + NB_MOD) {
        // ================= conv roles =================
        bool isOff = bid < NB_OFF;
        int id = isOff ? bid : bid - NB_OFF;
        int bx, gsel, b;
        if (isOff) { bx = id % 72; gsel = (id / 72) & 3; b = id / 288; }
        else       { bx = id % 72; gsel = (id / 72) & 1; b = id / 144; }
        int th = (bx / 6) * 16, tw = (bx % 6) * 32;
        int lyy = tid >> 4, lxx = tid & 15;
        int nchunk = isOff ? 4 : 8;

        float4 acc0[5], acc1[5];
        #pragma unroll
        for (int j = 0; j < 5; j++) { acc0[j] = make_float4(0,0,0,0); acc1[j] = make_float4(0,0,0,0); }

        for (int chunk = 0; chunk < nchunk; chunk++) {
            const float* base;
            if (isOff)
                base = (chunk < 2 ? wr : src) + (size_t)(b*Cn + gsel*CGn + (chunk&1)*8)*HWn;
            else
                base = wr + (size_t)(b*Cn + chunk*8)*HWn;
            __syncthreads();
            for (int i = tid; i < 1440; i += 256) {
                int c = i / 180; int r = i % 180; int widx = r / 20; int o = r % 20;
                float v = 0.f;
                if (o < 18) {
                    if (isOff) v = ow[(size_t)(o*32 + chunk*8 + c)*9 + widx];
                    else       v = mw[(size_t)((gsel*18 + o)*Cn + chunk*8 + c)*9 + widx];
                }
                sWp[i] = v;
            }
            for (int i = tid; i < 8*18*35; i += 256) {
                int c = i / 630; int r2 = i % 630; int rr = r2 / 35; int cc = r2 % 35;
                int y = th + rr - 1, x = tw + cc - 1;
                float v = 0.f;
                if (cc < 34 && (unsigned)y < (unsigned)Hn && (unsigned)x < (unsigned)Wn)
                    v = base[c*HWn + y*Wn + x];
                sT[i] = v;
            }
            __syncthreads();
            for (int c = 0; c < 8; c++) {
                #pragma unroll
                for (int kh = 0; kh < 3; kh++) {
                    const float* rowp = sT + c*630 + (lyy+kh)*35 + 2*lxx;
                    float xv[4];
                    xv[0] = rowp[0]; xv[1] = rowp[1]; xv[2] = rowp[2]; xv[3] = rowp[3];
                    #pragma unroll
                    for (int kw = 0; kw < 3; kw++) {
                        const float4* wp = (const float4*)(sWp + (c*9 + kh*3 + kw)*20);
                        float a0 = xv[kw], a1 = xv[kw+1];
                        #pragma unroll
                        for (int j = 0; j < 5; j++) {
                            float4 wv = wp[j];
                            acc0[j].x = fmaf(a0, wv.x, acc0[j].x); acc1[j].x = fmaf(a1, wv.x, acc1[j].x);
                            acc0[j].y = fmaf(a0, wv.y, acc0[j].y); acc1[j].y = fmaf(a1, wv.y, acc1[j].y);
                            acc0[j].z = fmaf(a0, wv.z, acc0[j].z); acc1[j].z = fmaf(a1, wv.z, acc1[j].z);
                            acc0[j].w = fmaf(a0, wv.w, acc0[j].w); acc1[j].w = fmaf(a1, wv.w, acc1[j].w);
                        }
                    }
                }
            }
        }
        int h = th + lyy, w = tw + 2*lxx;
        const float* a0 = (const float*)acc0;
        const float* a1 = (const float*)acc1;
        if (isOff) {
            #pragma unroll
            for (int o = 0; o < 18; o++) {
                float bo = obv[o];
                float2 r;
                r.x = 50.f * tanhf(0.5f * (a0[o] + bo));
                r.y = 50.f * tanhf(0.5f * (a1[o] + bo));
                *(float2*)(offout + (size_t)(b*72 + gsel*18 + o)*HWn + h*Wn + w) = r;
            }
        } else {
            #pragma unroll
            for (int o = 0; o < 18; o++) {
                float bo = mbv[gsel*18 + o];
                float2 r;
                r.x = 1.f + tanhf(0.5f * (a0[o] + bo));
                r.y = 1.f + tanhf(0.5f * (a1[o] + bo));
                *(float2*)(g_mod + (size_t)(b*36 + gsel*18 + o)*HWn + h*Wn + w) = r;
            }
        }
    } else if (bid < NB_OFF + NB_MOD + NB_TR) {
        // ================= transpose role =================
        int id  = bid - (NB_OFF + NB_MOD);
        int hw0 = (id % 1152) * 32;
        int c0  = ((id / 1152) & 1) * 32;
        int b   = id / 2304;
        int tx  = tid & 31, ty = tid >> 5;
        float (*t)[33] = (float(*)[33])sT;
        #pragma unroll
        for (int i = 0; i < 4; i++) {
            int c = c0 + ty + i*8;
            t[ty + i*8][tx] = wr[(size_t)(b*Cn + c)*HWn + hw0 + tx];
        }
        __syncthreads();
        #pragma unroll
        for (int i = 0; i < 4; i++) {
            int hw = hw0 + ty + i*8;
            g_xnhwc[(size_t)(b*HWn + hw)*Cn + c0 + tx] = t[tx][ty + i*8];
        }
    } else {
        // ================= weight re-layout role =================
        int i = (bid - (NB_OFF + NB_MOD + NB_TR))*256 + tid;
        if (i < Gn*Kn*1024) {
            int e  = i & 3;
            int q  = (i >> 2) & 1;
            int j2 = (i >> 3) & 15;
            int cc = (i >> 7) & 7;
            int gk = i >> 10;
            int k  = gk % 9;
            int g  = gk / 9;
            int c  = q*8 + cc;
            int co = j2*4 + e;
            g_wTu[i] = rw[(size_t)(co*Cn + g*CGn + c)*Kn + k];
        }
    }
}

// ---------------------------------------------------------------------------
// Deformable conv v6 + k-unroll 3: thread = (pixel, channel-HALF q in {0,1}).
// Lane q gathers 8 channels (2x float4) and contracts into all 64 co
// (32 f32x2 accs). Per-warp k-phase rotation; unroll 3 lets ptxas batch
// up to 24 corner LDGs per chain. Butterfly (xor 1) at the end.
// ---------------------------------------------------------------------------
__global__ void __launch_bounds__(256, 2) k_deform(
        const float* __restrict__ offmap, float* __restrict__ out) {
    __shared__ float sW[Kn*1024];     // [k][cc8][j2][q2][e4] = 9216 floats
    int tid  = threadIdx.x;
    int lane = tid & 31;
    int pxw  = lane >> 1;             // pixel within warp (0..15)
    int q    = lane & 1;              // channel half (0..1)
    int wid  = tid >> 5;
    int px   = wid*16 + pxw;          // pixel within block (0..127)
    int p0   = blockIdx.x * 128;
    int b    = p0 / HWn;
    int hw   = p0 - b*HWn + px;
    int h    = hw / Wn, w = hw - h*Wn;
    int k0   = wid % 9;               // per-warp k phase

    ull acc[32];
    #pragma unroll
    for (int j = 0; j < 32; j++) acc[j] = 0ull;

    const float* xb = g_xnhwc + (size_t)b*HWn*Cn;

    for (int g = 0; g < Gn; g++) {
        __syncthreads();
        {
            const float* wg = g_wTu + g*(Kn*1024);
            for (int i = tid; i < Kn*1024; i += 256) sW[i] = wg[i];
        }
        __syncthreads();

        const float* offb = offmap + (size_t)(b*72 + g*18)*HWn + hw;
        const float* modb = g_mod  + (size_t)(b*36 + g*9 )*HWn + hw;
        const float* xg   = xb + g*CGn + q*8;

        #pragma unroll 3
        for (int kk = 0; kk < 9; kk++) {
            int k = kk + k0; if (k >= 9) k -= 9;
            // ---- gather: this lane's 8 channels of its pixel ----
            float oy = offb[(2*k  )*HWn];
            float ox = offb[(2*k+1)*HWn];
            float m  = modb[k*HWn];
            float yf = oy + (float)(k/3 + h - 1);
            float xf = ox + (float)(k%3 + w - 1);
            float y0f = floorf(yf), x0f = floorf(xf);
            int   y0  = (int)y0f,   x0  = (int)x0f;
            float ly = yf - y0f, lx = xf - x0f;
            float cw0 = (1.f-ly)*(1.f-lx)*m;
            float cw1 = (1.f-ly)*lx*m;
            float cw2 = ly*(1.f-lx)*m;
            float cw3 = ly*lx*m;
            float4 va = make_float4(0.f,0.f,0.f,0.f);
            float4 vb = make_float4(0.f,0.f,0.f,0.f);
            #pragma unroll
            for (int corner = 0; corner < 4; corner++) {
                int yi = y0 + (corner >> 1);
                int xi = x0 + (corner & 1);
                float wc = (corner==0)?cw0:(corner==1)?cw1:(corner==2)?cw2:cw3;
                if ((unsigned)yi < (unsigned)Hn && (unsigned)xi < (unsigned)Wn) {
                    const float4* pp = (const float4*)(xg + (size_t)(yi*Wn + xi)*Cn);
                    float4 xa = pp[0];
                    float4 xbv = pp[1];
                    va.x = fmaf(wc, xa.x, va.x);  va.y = fmaf(wc, xa.y, va.y);
                    va.z = fmaf(wc, xa.z, va.z);  va.w = fmaf(wc, xa.w, va.w);
                    vb.x = fmaf(wc, xbv.x, vb.x); vb.y = fmaf(wc, xbv.y, vb.y);
                    vb.z = fmaf(wc, xbv.z, vb.z); vb.w = fmaf(wc, xbv.w, vb.w);
                }
            }
            // ---- contract my 8 channels into all 64 co ----
            float cv[8] = {va.x, va.y, va.z, va.w, vb.x, vb.y, vb.z, vb.w};
            #pragma unroll
            for (int cc = 0; cc < 8; cc++) {
                ull vp = pk2(cv[cc]);
                const float* rp = sW + ((k*8 + cc) << 7) + q*4;
                #pragma unroll
                for (int j2 = 0; j2 < 16; j2++) {
                    ulonglong2 wv = *(const ulonglong2*)(rp + j2*8);
                    fma2(acc[2*j2],   vp, wv.x);
                    fma2(acc[2*j2+1], vp, wv.y);
                }
            }
        }
    }

    // butterfly reduction over the 2 q-lanes of each pixel
    float2 af[32];
    #pragma unroll
    for (int t = 0; t < 32; t++) af[t] = upk(acc[t]);
    #pragma unroll
    for (int t = 0; t < 32; t++) {
        af[t].x += __shfl_xor_sync(0xffffffffu, af[t].x, 1);
        af[t].y += __shfl_xor_sync(0xffffffffu, af[t].y, 1);
    }

    // lane q writes co pairs t = q*16 .. q*16+15  (co = 2t, 2t+1)
    float* ob = out + (size_t)b*Cn*HWn + hw;
    #pragma unroll
    for (int r = 0; r < 16; r++) {
        int t = q*16 + r;
        ob[(size_t)(2*t  )*HWn] = af[t].x;
        ob[(size_t)(2*t+1)*HWn] = af[t].y;
    }
}

// ---------------------------------------------------------------------------
extern "C" void kernel_launch(void* const* d_in, const int* in_sizes, int n_in,
                              void* d_out, int out_size) {
    const float* wr  = (const float*)d_in[0];
    const float* src = (const float*)d_in[1];
    const float* ow  = (const float*)d_in[2];
    const float* obv = (const float*)d_in[3];
    const float* mw  = (const float*)d_in[4];
    const float* mbv = (const float*)d_in[5];
    const float* rw  = (const float*)d_in[6];

    float* out    = (float*)d_out;
    float* offout = out + (size_t)Bn*Cn*HWn;

    k_prep  <<<NB_ALL, 256>>>(wr, src, ow, obv, mw, mbv, rw, offout);
    k_deform<<<Bn*HWn/128, 256>>>(offout, out);
}